// round 14
// baseline (speedup 1.0000x reference)
#include <cuda_runtime.h>
#include <cuda_bf16.h>
#include <cfloat>
#include <cmath>

#define BB 32
#define NN 256
#define LL 50
#define BN (BB * NN)          // 8192
#define DU 32
#define DI 32
#define DC 16
#define DD 48
#define FEAT 128

typedef unsigned long long ull;

// ---------------- scratch (no allocs allowed) ----------------
__device__ float g_feat[BN * FEAT];
__device__ float g_logits[BN];
__device__ __align__(16) ull g_Wbc2[24 * 64]; // (b-c) k-pairs, [kp][j]
__device__ __align__(16) ull g_Wac2[24 * 64]; // (a+c) k-pairs
__device__ __align__(16) ull g_Wd2 [24 * 64]; // d k-pairs
__device__ float g_v[64];                     // w2 @ w3
__device__ float g_cs[1];                     // b2.w3 + b3
__device__ int   g_cnt_b[BB];                 // batch completion counters

// ---------------- helpers ----------------
__device__ __forceinline__ void ffma2(ull& acc, ull a, ull b) {
    asm("fma.rn.f32x2 %0, %1, %2, %0;" : "+l"(acc) : "l"(a), "l"(b));
}
__device__ __forceinline__ void upk(ull v, float& x, float& y) {
    asm("mov.b64 {%0,%1}, %2;" : "=f"(x), "=f"(y) : "l"(v));
}
__device__ __forceinline__ ull pk(float x, float y) {
    ull r;
    asm("mov.b64 %0, {%1,%2};" : "=l"(r) : "f"(x), "f"(y));
    return r;
}
__device__ __forceinline__ unsigned sptr(const void* p) {
    return (unsigned)__cvta_generic_to_shared(p);
}
__device__ __forceinline__ void lds_v2u64(unsigned addr, ull& a, ull& b) {
    asm("ld.shared.v2.u64 {%0,%1}, [%2];" : "=l"(a), "=l"(b) : "r"(addr));
}
__device__ __forceinline__ void sts_u64(unsigned addr, ull v) {
    asm("st.shared.u64 [%0], %1;" :: "r"(addr), "l"(v));
}
__device__ __forceinline__ void cpasync16(unsigned dst, const void* src) {
    asm volatile("cp.async.ca.shared.global [%0], [%1], 16;"
                 :: "r"(dst), "l"(src));
}
__device__ __forceinline__ void cpasync_wait_all() {
    asm volatile("cp.async.commit_group;\ncp.async.wait_group 0;" ::: "memory");
}

// ---------------- K0: fold weights + zero counters ----------------
__global__ void setup_kernel(const float* __restrict__ w1,
                             const float* __restrict__ w2,
                             const float* __restrict__ w3,
                             const float* __restrict__ b2,
                             const float* __restrict__ b3)
{
    int e = blockIdx.x * 256 + threadIdx.x;
    if (blockIdx.x < 6) {           // 1536 elements: (kp, j)
        int kp = e / 64, j = e % 64;
        int k0 = 2 * kp, k1 = 2 * kp + 1;
        float a0 = w1[k0 * 64 + j];
        float b0 = w1[(48 + k0) * 64 + j];
        float c0 = w1[(96 + k0) * 64 + j];
        float d0 = w1[(144 + k0) * 64 + j];
        float a1 = w1[k1 * 64 + j];
        float bb1 = w1[(48 + k1) * 64 + j];
        float c1 = w1[(96 + k1) * 64 + j];
        float d1 = w1[(144 + k1) * 64 + j];
        g_Wbc2[e] = pk(b0 - c0, bb1 - c1);
        g_Wac2[e] = pk(a0 + c0, a1 + c1);
        g_Wd2[e]  = pk(d0, d1);
    } else {
        int t = threadIdx.x;
        if (t < 64) {
            float v = 0.f;
#pragma unroll
            for (int m = 0; m < 16; m++) v += w2[t * 16 + m] * w3[m];
            g_v[t] = v;
        } else if (t == 64) {
            float cs = b3[0];
#pragma unroll
            for (int m = 0; m < 16; m++) cs += b2[m] * w3[m];
            g_cs[0] = cs;
        }
        if (t >= 128 && t < 128 + BB) g_cnt_b[t - 128] = 0;
    }
}

// ---------------- K1: attention, 2 bn per CTA ----------------
// Halves: threads 0-127 -> bn0, 128-255 -> bn1 for gather/score/pooled.
// Fold: threads 0-127 single-pass DUAL-Q (read W once, fold both bn).
__global__ void __launch_bounds__(256, 2) attn_kernel(
    const float* __restrict__ emb_user,
    const float* __restrict__ emb_item,
    const float* __restrict__ emb_cate,
    const float* __restrict__ b1,
    const int* __restrict__ user,
    const int* __restrict__ items,
    const int* __restrict__ items_cate,
    const int* __restrict__ ii,
    const int* __restrict__ iic)
{
    const int bn0   = blockIdx.x * 2;
    const int t     = threadIdx.x;
    const int tt    = t & 127;      // thread within half
    const int bh    = t >> 7;       // which bn this thread serves
    const int bnme  = bn0 + bh;
    const int w     = t >> 5;       // 0..7
    const int lane  = t & 31;
    const int jq    = lane & 15;
    const int khalf = lane >> 4;

    __shared__ __align__(16) ull   Mx[2][24 * 64];     // 24.6 KB
    __shared__ __align__(16) float he_s[2][LL][52];    // 20.8 KB
    __shared__ __align__(16) float S[2][LL][20];       // 8.0 KB
    __shared__ __align__(16) float q_s[2][48];
    __shared__ float cn_part[2][2][64];                // [bh][half][j]
    __shared__ float v_s[64];
    __shared__ float sc_s[2][LL];
    __shared__ int   idx_s[2][LL];

    // ================= phase 1 (no barrier until cp.async wait) ==========
    // (a) he gathers via cp.async — each half gathers its own bn
    {
        const unsigned heb = sptr(&he_s[bh][0][0]);
#pragma unroll
        for (int u = 0; u < 5; u++) {
            int idx = tt + u * 128;
            if (idx < LL * 12) {
                int row = idx / 12, c = idx % 12;
                const float* src;
                if (c < 8) {
                    int e = __ldg(&ii[bnme * LL + row]);
                    src = emb_item + (size_t)e * DI + c * 4;
                } else {
                    int e = __ldg(&iic[bnme * LL + row]);
                    src = emb_cate + (size_t)e * DC + (c - 8) * 4;
                }
                cpasync16(heb + row * 208 + c * 16, src);
            }
        }
    }

    // (b) stage q, v, mask indices (per half)
    {
        const int it = __ldg(&items[bnme]);
        const int ic = __ldg(&items_cate[bnme]);
        if (tt < 32)       q_s[bh][tt] = __ldg(&emb_item[(size_t)it * DI + tt]);
        else if (tt < 48)  q_s[bh][tt] = __ldg(&emb_cate[(size_t)ic * DC + (tt - 32)]);
        if (bh == 0 && tt < 64) v_s[tt] = g_v[tt];
        if (tt >= 64 && tt < 64 + LL)
            idx_s[bh][tt - 64] = __ldg(&ii[bnme * LL + (tt - 64)]);
    }

    // (c) dual-q fold by threads 0-127: read W once, fold BOTH bn
    if (t < 128) {
        const int j = t & 63;
        const int half = t >> 6;
        const int it0 = __ldg(&items[bn0]);
        const int ic0 = __ldg(&items_cate[bn0]);
        const int it1 = __ldg(&items[bn0 + 1]);
        const int ic1 = __ldg(&items_cate[bn0 + 1]);
        const ull* qi0 = (const ull*)(emb_item + (size_t)it0 * DI);
        const ull* qc0 = (const ull*)(emb_cate + (size_t)ic0 * DC);
        const ull* qi1 = (const ull*)(emb_item + (size_t)it1 * DI);
        const ull* qc1 = (const ull*)(emb_cate + (size_t)ic1 * DC);
        const ull* wbcp = g_Wbc2 + half * 12 * 64 + j;
        const ull* wacp = g_Wac2 + half * 12 * 64 + j;
        const ull* wdp  = g_Wd2  + half * 12 * 64 + j;
        unsigned mxb0 = sptr(&Mx[0][0]) + j * 8 + half * 12 * 512;
        unsigned mxb1 = sptr(&Mx[1][0]) + j * 8 + half * 12 * 512;
        ull cn0acc = 0ull, cn1acc = 0ull;
#pragma unroll
        for (int kp = 0; kp < 12; kp++) {
            const int kpg = half * 12 + kp;
            ull qp0 = (kpg < 16) ? __ldg(&qi0[kpg]) : __ldg(&qc0[kpg - 16]);
            ull qp1 = (kpg < 16) ? __ldg(&qi1[kpg]) : __ldg(&qc1[kpg - 16]);
            ull wbc = __ldg(&wbcp[kp * 64]);
            ull wd  = __ldg(&wdp[kp * 64]);
            ull wac = __ldg(&wacp[kp * 64]);
            ull m0 = wbc;
            ffma2(m0, qp0, wd);
            sts_u64(mxb0 + kp * 512, m0);
            ull m1 = wbc;
            ffma2(m1, qp1, wd);
            sts_u64(mxb1 + kp * 512, m1);
            ffma2(cn0acc, qp0, wac);
            ffma2(cn1acc, qp1, wac);
        }
        float cx, cy;
        float bias = (half == 0) ? b1[j] : 0.f;
        upk(cn0acc, cx, cy);
        cn_part[0][half][j] = cx + cy + bias;
        upk(cn1acc, cx, cy);
        cn_part[1][half][j] = cx + cy + bias;
    }
    cpasync_wait_all();
    __syncthreads();

    // ================= phase 2: score ======================================
    // warp w: half wh = w>>2, l-chunk wl = w&3.
    // lane: cols {2jq, 2jq+1, 2jq+32, 2jq+33}, k-half = khalf.
    const int wh = w >> 2;
    ull A0[12], A1[12], A2[12], A3[12];
    {
        unsigned mb = sptr(&Mx[wh][0]) + khalf * 12 * 512 + jq * 16;
#pragma unroll
        for (int i = 0; i < 12; i++) {
            lds_v2u64(mb + i * 512,       A0[i], A1[i]);
            lds_v2u64(mb + i * 512 + 256, A2[i], A3[i]);
        }
    }
    const int c0 = 2 * jq, c2 = 2 * jq + 32;
    const float cn0 = cn_part[wh][0][c0]     + cn_part[wh][1][c0];
    const float cn1 = cn_part[wh][0][c0 + 1] + cn_part[wh][1][c0 + 1];
    const float cn2 = cn_part[wh][0][c2]     + cn_part[wh][1][c2];
    const float cn3 = cn_part[wh][0][c2 + 1] + cn_part[wh][1][c2 + 1];
    const float v0 = v_s[c0], v1 = v_s[c0 + 1];
    const float v2 = v_s[c2], v3 = v_s[c2 + 1];

    const int wl  = w & 3;
    const int l0  = (wl < 2) ? wl * 13 : 26 + (wl - 2) * 12;
    const int cnt = (wl < 2) ? 13 : 12;
    for (int li = 0; li < cnt; li++) {
        const int l = l0 + li;
        unsigned hb = sptr(&he_s[wh][l][0]) + khalf * 96;
        ull a0 = 0ull, a1 = 0ull, a2 = 0ull, a3 = 0ull;
#pragma unroll
        for (int c = 0; c < 6; c++) {
            ull h0, h1;
            lds_v2u64(hb + c * 16, h0, h1);
            ffma2(a0, h0, A0[2 * c]);
            ffma2(a0, h1, A0[2 * c + 1]);
            ffma2(a1, h0, A1[2 * c]);
            ffma2(a1, h1, A1[2 * c + 1]);
            ffma2(a2, h0, A2[2 * c]);
            ffma2(a2, h1, A2[2 * c + 1]);
            ffma2(a3, h0, A3[2 * c]);
            ffma2(a3, h1, A3[2 * c + 1]);
        }
        float x, y;
        upk(a0, x, y); float p0 = x + y;
        upk(a1, x, y); float p1 = x + y;
        upk(a2, x, y); float p2 = x + y;
        upk(a3, x, y); float p3 = x + y;
        p0 += __shfl_xor_sync(0xffffffffu, p0, 16);
        p1 += __shfl_xor_sync(0xffffffffu, p1, 16);
        p2 += __shfl_xor_sync(0xffffffffu, p2, 16);
        p3 += __shfl_xor_sync(0xffffffffu, p3, 16);
        float s;
        s  = fmaxf(p0 + cn0, 0.f) * v0;
        s  = fmaf(fmaxf(p1 + cn1, 0.f), v1, s);
        s  = fmaf(fmaxf(p2 + cn2, 0.f), v2, s);
        s  = fmaf(fmaxf(p3 + cn3, 0.f), v3, s);
        S[wh][l][jq] = s;
    }
    __syncthreads();

    // ================= phase 3: score reduce (pair-split, per half) =======
    if (tt < 100) {
        const int l = tt >> 1, h = tt & 1;
        const float4* sp = (const float4*)&S[bh][l][h * 8];
        float4 r0 = sp[0], r1 = sp[1];
        float sum8 = (r0.x + r0.y) + (r0.z + r0.w)
                   + (r1.x + r1.y) + (r1.z + r1.w);
        unsigned mk = ((tt & 96) == 96) ? 0xfu : 0xffffffffu;
        float tot = sum8 + __shfl_xor_sync(mk, sum8, 1);
        if (h == 0)
            sc_s[bh][l] = (idx_s[bh][l] == 0) ? 0.f : (tot + g_cs[0]);
    }
    __syncthreads();

    // ================= phase 4: pooled + feat (per half) ==================
    float* fo = g_feat + (size_t)bnme * FEAT;
    if (tt < 48) {
        float pooled = 0.f;
#pragma unroll 10
        for (int l = 0; l < LL; l++)
            pooled = fmaf(sc_s[bh][l], he_s[bh][l][tt], pooled);
        fo[tt]      = q_s[bh][tt];
        fo[48 + tt] = pooled;
    } else if (tt < 80) {
        fo[96 + (tt - 48)] =
            __ldg(&emb_user[(size_t)__ldg(&user[bnme]) * DU + (tt - 48)]);
    }
}

// ---------------- K2: FC MLP (32 rows/CTA) + fused softmax ----------------
#define ROWS 32
__global__ void __launch_bounds__(256) fc_kernel(
    const float* __restrict__ fw1, const float* __restrict__ fb1,
    const float* __restrict__ fw2, const float* __restrict__ fb2,
    const float* __restrict__ fw3, const float* __restrict__ fb3,
    const int* __restrict__ items, float* __restrict__ out)
{
    const int t = threadIdx.x;
    const int row0 = blockIdx.x * ROWS;

    __shared__ __align__(16) float fs[ROWS][132];   // 16.9 KB
    __shared__ __align__(16) float x1[ROWS][204];   // 26.1 KB
    __shared__ __align__(16) float x2[ROWS][84];    // 10.8 KB

    const float4* src = (const float4*)(g_feat + (size_t)row0 * FEAT);
    for (int i = t; i < ROWS * FEAT / 4; i += 256) {
        float4 v = src[i];
        int r = i >> 5, c = (i & 31) * 4;
        fs[r][c] = v.x; fs[r][c + 1] = v.y;
        fs[r][c + 2] = v.z; fs[r][c + 3] = v.w;
    }
    __syncthreads();

    // fc1: 200 threads: jjq = t%50 (4 jj), rowgroup = (t/50)*8 (8 rows)
    if (t < 200) {
        const int jjq = t % 50;
        const int rg  = (t / 50) * 8;
        const float* wbase = fw1 + 4 * jjq;
        const ull b0  = pk(fb1[4 * jjq],     fb1[4 * jjq + 1]);
        const ull b1v = pk(fb1[4 * jjq + 2], fb1[4 * jjq + 3]);
        ull acc[8][2];
#pragma unroll
        for (int r = 0; r < 8; r++) { acc[r][0] = b0; acc[r][1] = b1v; }
#pragma unroll 4
        for (int i = 0; i < FEAT; i++) {
            float4 wv = __ldg((const float4*)(wbase + i * 200));
            ull wp0 = pk(wv.x, wv.y);
            ull wp1 = pk(wv.z, wv.w);
#pragma unroll
            for (int r = 0; r < 8; r++) {
                float xv = fs[rg + r][i];
                ull xx = pk(xv, xv);
                ffma2(acc[r][0], xx, wp0);
                ffma2(acc[r][1], xx, wp1);
            }
        }
#pragma unroll
        for (int r = 0; r < 8; r++) {
            float h0, h1, h2, h3;
            upk(acc[r][0], h0, h1);
            upk(acc[r][1], h2, h3);
            float4 o;
            o.x = fmaxf(h0, 0.f); o.y = fmaxf(h1, 0.f);
            o.z = fmaxf(h2, 0.f); o.w = fmaxf(h3, 0.f);
            *(float4*)&x1[rg + r][4 * jjq] = o;
        }
    }
    __syncthreads();

    // fc2: 160 threads: jjq = t%20 (4 jj), rowgroup = (t/20)*4 (4 rows)
    if (t < 160) {
        const int jjq = t % 20;
        const int rg  = (t / 20) * 4;
        const float* wbase = fw2 + 4 * jjq;
        const ull b0  = pk(fb2[4 * jjq],     fb2[4 * jjq + 1]);
        const ull b1v = pk(fb2[4 * jjq + 2], fb2[4 * jjq + 3]);
        ull acc[4][2];
#pragma unroll
        for (int r = 0; r < 4; r++) { acc[r][0] = b0; acc[r][1] = b1v; }
#pragma unroll 4
        for (int i = 0; i < 200; i++) {
            float4 wv = __ldg((const float4*)(wbase + i * 80));
            ull wp0 = pk(wv.x, wv.y);
            ull wp1 = pk(wv.z, wv.w);
#pragma unroll
            for (int r = 0; r < 4; r++) {
                float xv = x1[rg + r][i];
                ull xx = pk(xv, xv);
                ffma2(acc[r][0], xx, wp0);
                ffma2(acc[r][1], xx, wp1);
            }
        }
#pragma unroll
        for (int r = 0; r < 4; r++) {
            float h0, h1, h2, h3;
            upk(acc[r][0], h0, h1);
            upk(acc[r][1], h2, h3);
            float4 o;
            o.x = fmaxf(h0, 0.f); o.y = fmaxf(h1, 0.f);
            o.z = fmaxf(h2, 0.f); o.w = fmaxf(h3, 0.f);
            *(float4*)&x2[rg + r][4 * jjq] = o;
        }
    }
    __syncthreads();

    // fc3 + sigmoid (32 rows)
    if (t < ROWS) {
        const ull* wp = (const ull*)fw3;
        const ull* xp = (const ull*)&x2[t][0];
        ull acc = 0ull;
#pragma unroll
        for (int ip = 0; ip < 40; ip++)
            ffma2(acc, xp[ip], __ldg(&wp[ip]));
        float a, b;
        upk(acc, a, b);
        float s = a + b + fb3[0];
        g_logits[row0 + t] = 1.0f / (1.0f + expf(-s));
    }

    // ---- fused softmax: last fc group (of 8) per batch runs it ----
    __threadfence();
    __syncthreads();
    __shared__ int sb_flag;
    if (t == 0) {
        int old = atomicAdd(&g_cnt_b[row0 >> 8], 1);
        sb_flag = (old == 7);
    }
    __syncthreads();
    if (!sb_flag) return;
    __threadfence();   // acquire: make other groups' logits visible

    const int base = (row0 >> 8) * NN;
    const int wid = t >> 5, lane = t & 31;
    __shared__ float red[8];
    __shared__ float smx, ssum;

    float l = g_logits[base + t];
    bool masked = (items[base + t] == 0);
    float val = masked ? -FLT_MAX : l;

    float mx = val;
#pragma unroll
    for (int o = 16; o > 0; o >>= 1)
        mx = fmaxf(mx, __shfl_down_sync(0xffffffffu, mx, o));
    if (lane == 0) red[wid] = mx;
    __syncthreads();
    if (t == 0) {
        float m = red[0];
#pragma unroll
        for (int w2i = 1; w2i < 8; w2i++) m = fmaxf(m, red[w2i]);
        smx = m;
    }
    __syncthreads();
    float m = smx;

    float e = masked ? 0.0f : expf(l - m);
    float sum = e;
#pragma unroll
    for (int o = 16; o > 0; o >>= 1)
        sum += __shfl_down_sync(0xffffffffu, sum, o);
    if (lane == 0) red[wid] = sum;
    __syncthreads();
    if (t == 0) {
        float s = 0.0f;
#pragma unroll
        for (int w2i = 0; w2i < 8; w2i++) s += red[w2i];
        ssum = s;
    }
    __syncthreads();

    out[base + t] = e / ssum;
}

// ---------------- launch ----------------
extern "C" void kernel_launch(void* const* d_in, const int* in_sizes, int n_in,
                              void* d_out, int out_size)
{
    const float* emb_user  = (const float*)d_in[0];
    const float* emb_item  = (const float*)d_in[1];
    const float* emb_cate  = (const float*)d_in[2];
    const float* att_w1    = (const float*)d_in[3];
    const float* att_b1    = (const float*)d_in[4];
    const float* att_w2    = (const float*)d_in[5];
    const float* att_b2    = (const float*)d_in[6];
    const float* att_w3    = (const float*)d_in[7];
    const float* att_b3    = (const float*)d_in[8];
    const float* fc_w1     = (const float*)d_in[9];
    const float* fc_b1     = (const float*)d_in[10];
    const float* fc_w2     = (const float*)d_in[11];
    const float* fc_b2     = (const float*)d_in[12];
    const float* fc_w3     = (const float*)d_in[13];
    const float* fc_b3     = (const float*)d_in[14];
    const int*   user      = (const int*)d_in[15];
    const int*   items     = (const int*)d_in[16];
    const int*   items_cate= (const int*)d_in[17];
    const int*   ii        = (const int*)d_in[18];
    const int*   iic       = (const int*)d_in[19];
    float* out = (float*)d_out;

    setup_kernel<<<7, 256>>>(att_w1, att_w2, att_w3, att_b2, att_b3);
    attn_kernel<<<BN / 2, 256>>>(emb_user, emb_item, emb_cate, att_b1,
                                 user, items, items_cate, ii, iic);
    fc_kernel<<<BN / ROWS, 256>>>(fc_w1, fc_b1, fc_w2, fc_b2, fc_w3, fc_b3,
                                  items, out);
}

// round 15
// speedup vs baseline: 1.0236x; 1.0236x over previous
#include <cuda_runtime.h>
#include <cuda_bf16.h>
#include <cfloat>
#include <cmath>

#define BB 32
#define NN 256
#define LL 50
#define BN (BB * NN)          // 8192
#define DU 32
#define DI 32
#define DC 16
#define DD 48
#define FEAT 128

typedef unsigned long long ull;

// ---------------- scratch (no allocs allowed) ----------------
__device__ float g_feat[BN * FEAT];
__device__ float g_logits[BN];
__device__ __align__(16) ull g_Wbc2[24 * 64]; // (b-c) k-pairs, [kp][j]
__device__ __align__(16) ull g_Wac2[24 * 64]; // (a+c) k-pairs
__device__ __align__(16) ull g_Wd2 [24 * 64]; // d k-pairs
__device__ float g_v[64];                     // w2 @ w3
__device__ float g_cs[1];                     // b2.w3 + b3
__device__ int   g_cnt_b[BB];                 // batch completion counters

// ---------------- helpers ----------------
__device__ __forceinline__ void ffma2(ull& acc, ull a, ull b) {
    asm("fma.rn.f32x2 %0, %1, %2, %0;" : "+l"(acc) : "l"(a), "l"(b));
}
__device__ __forceinline__ void upk(ull v, float& x, float& y) {
    asm("mov.b64 {%0,%1}, %2;" : "=f"(x), "=f"(y) : "l"(v));
}
__device__ __forceinline__ ull pk(float x, float y) {
    ull r;
    asm("mov.b64 %0, {%1,%2};" : "=l"(r) : "f"(x), "f"(y));
    return r;
}
__device__ __forceinline__ unsigned sptr(const void* p) {
    return (unsigned)__cvta_generic_to_shared(p);
}
__device__ __forceinline__ void lds_v2u64(unsigned addr, ull& a, ull& b) {
    asm("ld.shared.v2.u64 {%0,%1}, [%2];" : "=l"(a), "=l"(b) : "r"(addr));
}
__device__ __forceinline__ void sts_u64(unsigned addr, ull v) {
    asm("st.shared.u64 [%0], %1;" :: "r"(addr), "l"(v));
}
__device__ __forceinline__ void cpasync16(unsigned dst, const void* src) {
    asm volatile("cp.async.ca.shared.global [%0], [%1], 16;"
                 :: "r"(dst), "l"(src));
}
__device__ __forceinline__ void cpasync_wait_all() {
    asm volatile("cp.async.commit_group;\ncp.async.wait_group 0;" ::: "memory");
}

// ---------------- K0: fold weights + zero counters ----------------
__global__ void setup_kernel(const float* __restrict__ w1,
                             const float* __restrict__ w2,
                             const float* __restrict__ w3,
                             const float* __restrict__ b2,
                             const float* __restrict__ b3)
{
    int e = blockIdx.x * 256 + threadIdx.x;
    if (blockIdx.x < 6) {           // 1536 elements: (kp, j)
        int kp = e / 64, j = e % 64;
        int k0 = 2 * kp, k1 = 2 * kp + 1;
        float a0 = w1[k0 * 64 + j];
        float b0 = w1[(48 + k0) * 64 + j];
        float c0 = w1[(96 + k0) * 64 + j];
        float d0 = w1[(144 + k0) * 64 + j];
        float a1 = w1[k1 * 64 + j];
        float bb1 = w1[(48 + k1) * 64 + j];
        float c1 = w1[(96 + k1) * 64 + j];
        float d1 = w1[(144 + k1) * 64 + j];
        g_Wbc2[e] = pk(b0 - c0, bb1 - c1);
        g_Wac2[e] = pk(a0 + c0, a1 + c1);
        g_Wd2[e]  = pk(d0, d1);
    } else {
        int t = threadIdx.x;
        if (t < 64) {
            float v = 0.f;
#pragma unroll
            for (int m = 0; m < 16; m++) v += w2[t * 16 + m] * w3[m];
            g_v[t] = v;
        } else if (t == 64) {
            float cs = b3[0];
#pragma unroll
            for (int m = 0; m < 16; m++) cs += b2[m] * w3[m];
            g_cs[0] = cs;
        }
        if (t >= 128 && t < 128 + BB) g_cnt_b[t - 128] = 0;
    }
}

// ---------------- K1: attention (R13 best — 1 bn per CTA) ----------------
__global__ void __launch_bounds__(128, 4) attn_kernel(
    const float* __restrict__ emb_user,
    const float* __restrict__ emb_item,
    const float* __restrict__ emb_cate,
    const float* __restrict__ b1,
    const int* __restrict__ user,
    const int* __restrict__ items,
    const int* __restrict__ items_cate,
    const int* __restrict__ ii,
    const int* __restrict__ iic)
{
    const int bn    = blockIdx.x;
    const int t     = threadIdx.x;
    const int w     = t >> 5;
    const int lane  = t & 31;
    const int jq    = lane & 15;
    const int khalf = lane >> 4;

    __shared__ __align__(16) float q_s[48];
    __shared__ __align__(16) ull Mx[24 * 64]; // [kp][j]
    __shared__ float cn_part[2][64];
    __shared__ float v_s[64];
    __shared__ __align__(16) float he_s[LL][52];
    __shared__ __align__(16) float S[LL][20];   // 80B rows, 16B-aligned
    __shared__ float sc_s[LL];
    __shared__ int   idx_s[LL];

    // ================= phase 1 (no barrier until cp.async wait) ==========
    {
        const unsigned heb = sptr(he_s);
#pragma unroll
        for (int u = 0; u < 5; u++) {
            int idx = t + u * 128;
            if (idx < LL * 12) {
                int row = idx / 12, c = idx % 12;
                const float* src;
                if (c < 8) {
                    int e = __ldg(&ii[bn * LL + row]);
                    src = emb_item + (size_t)e * DI + c * 4;
                } else {
                    int e = __ldg(&iic[bn * LL + row]);
                    src = emb_cate + (size_t)e * DC + (c - 8) * 4;
                }
                cpasync16(heb + row * 208 + c * 16, src);
            }
        }
    }

    {
        const int it = __ldg(&items[bn]);
        const int ic = __ldg(&items_cate[bn]);
        if (t < 32)       q_s[t] = __ldg(&emb_item[(size_t)it * DI + t]);
        else if (t < 48)  q_s[t] = __ldg(&emb_cate[(size_t)ic * DC + (t - 32)]);
        if (t < 64)       v_s[t] = g_v[t];
        if (t >= 64 && t < 64 + LL) idx_s[t - 64] = __ldg(&ii[bn * LL + (t - 64)]);
    }

    // fold (coalesced): j = t&63, k-half = t>>6
    {
        const int j = t & 63;
        const int half = t >> 6;
        const int it = __ldg(&items[bn]);
        const int ic = __ldg(&items_cate[bn]);
        const ull* qitem = (const ull*)(emb_item + (size_t)it * DI);
        const ull* qcate = (const ull*)(emb_cate + (size_t)ic * DC);
        const ull* wbcp = g_Wbc2 + half * 12 * 64 + j;
        const ull* wacp = g_Wac2 + half * 12 * 64 + j;
        const ull* wdp  = g_Wd2  + half * 12 * 64 + j;
        unsigned mxb = sptr(Mx) + j * 8 + half * 12 * 512;
        ull cnacc = 0ull;
#pragma unroll
        for (int kp = 0; kp < 12; kp++) {
            const int kpg = half * 12 + kp;
            ull qp = (kpg < 16) ? __ldg(&qitem[kpg]) : __ldg(&qcate[kpg - 16]);
            ull m = __ldg(&wbcp[kp * 64]);
            ffma2(m, qp, __ldg(&wdp[kp * 64]));
            sts_u64(mxb + kp * 512, m);
            ffma2(cnacc, qp, __ldg(&wacp[kp * 64]));
        }
        float cx, cy;
        upk(cnacc, cx, cy);
        cn_part[half][j] = cx + cy + ((half == 0) ? b1[j] : 0.f);
    }
    cpasync_wait_all();
    __syncthreads();

    // ================= phase 2: score ======================================
    // A-tile: cols {2jq, 2jq+1, 2jq+32, 2jq+33}, lane-contiguous loads.
    ull A0[12], A1[12], A2[12], A3[12];
    {
        unsigned mb = sptr(Mx) + khalf * 12 * 512 + jq * 16;
#pragma unroll
        for (int i = 0; i < 12; i++) {
            lds_v2u64(mb + i * 512,       A0[i], A1[i]);   // cols 2jq, 2jq+1
            lds_v2u64(mb + i * 512 + 256, A2[i], A3[i]);   // cols 32+2jq, 33+2jq
        }
    }
    const int c0 = 2 * jq, c2 = 2 * jq + 32;
    const float cn0 = cn_part[0][c0]     + cn_part[1][c0];
    const float cn1 = cn_part[0][c0 + 1] + cn_part[1][c0 + 1];
    const float cn2 = cn_part[0][c2]     + cn_part[1][c2];
    const float cn3 = cn_part[0][c2 + 1] + cn_part[1][c2 + 1];
    const float v0 = v_s[c0],     v1 = v_s[c0 + 1];
    const float v2 = v_s[c2],     v3 = v_s[c2 + 1];

    const int l0  = (w < 2) ? w * 13 : 26 + (w - 2) * 12;
    const int cnt = (w < 2) ? 13 : 12;
    for (int li = 0; li < cnt; li++) {
        const int l = l0 + li;
        unsigned hb = sptr(&he_s[l][0]) + khalf * 96;
        ull a0 = 0ull, a1 = 0ull, a2 = 0ull, a3 = 0ull;
#pragma unroll
        for (int c = 0; c < 6; c++) {
            ull h0, h1;
            lds_v2u64(hb + c * 16, h0, h1);
            ffma2(a0, h0, A0[2 * c]);
            ffma2(a0, h1, A0[2 * c + 1]);
            ffma2(a1, h0, A1[2 * c]);
            ffma2(a1, h1, A1[2 * c + 1]);
            ffma2(a2, h0, A2[2 * c]);
            ffma2(a2, h1, A2[2 * c + 1]);
            ffma2(a3, h0, A3[2 * c]);
            ffma2(a3, h1, A3[2 * c + 1]);
        }
        float x, y;
        upk(a0, x, y); float p0 = x + y;
        upk(a1, x, y); float p1 = x + y;
        upk(a2, x, y); float p2 = x + y;
        upk(a3, x, y); float p3 = x + y;
        p0 += __shfl_xor_sync(0xffffffffu, p0, 16);
        p1 += __shfl_xor_sync(0xffffffffu, p1, 16);
        p2 += __shfl_xor_sync(0xffffffffu, p2, 16);
        p3 += __shfl_xor_sync(0xffffffffu, p3, 16);
        float s;
        s  = fmaxf(p0 + cn0, 0.f) * v0;
        s  = fmaf(fmaxf(p1 + cn1, 0.f), v1, s);
        s  = fmaf(fmaxf(p2 + cn2, 0.f), v2, s);
        s  = fmaf(fmaxf(p3 + cn3, 0.f), v3, s);
        S[l][jq] = s;
    }
    __syncthreads();

    // ================= phase 3: score reduce (pair-split, contiguous) =====
    if (t < 100) {
        const int l = t >> 1, h = t & 1;
        const float4* sp = (const float4*)&S[l][h * 8];
        float4 r0 = sp[0], r1 = sp[1];
        float sum8 = (r0.x + r0.y) + (r0.z + r0.w)
                   + (r1.x + r1.y) + (r1.z + r1.w);
        unsigned mk = (t < 96) ? 0xffffffffu : 0xfu;
        float tot = sum8 + __shfl_xor_sync(mk, sum8, 1);
        if (h == 0)
            sc_s[l] = (idx_s[l] == 0) ? 0.f : (tot + g_cs[0]);
    }
    __syncthreads();

    // ================= phase 4: pooled + feat ==============================
    float* fo = g_feat + bn * FEAT;
    if (t < 48) {
        float pooled = 0.f;
#pragma unroll 10
        for (int l = 0; l < LL; l++)
            pooled = fmaf(sc_s[l], he_s[l][t], pooled);
        fo[t]      = q_s[t];
        fo[48 + t] = pooled;
    } else if (t < 80) {
        fo[96 + (t - 48)] = __ldg(&emb_user[(size_t)__ldg(&user[bn]) * DU + (t - 48)]);
    }
}

// ---------------- K2: FC MLP (32 rows/CTA) + fused softmax ----------------
#define ROWS 32
__global__ void __launch_bounds__(256) fc_kernel(
    const float* __restrict__ fw1, const float* __restrict__ fb1,
    const float* __restrict__ fw2, const float* __restrict__ fb2,
    const float* __restrict__ fw3, const float* __restrict__ fb3,
    const int* __restrict__ items, float* __restrict__ out)
{
    const int t = threadIdx.x;
    const int row0 = blockIdx.x * ROWS;

    __shared__ __align__(16) float fs[ROWS][132];   // 16.9 KB
    __shared__ __align__(16) float x1[ROWS][204];   // 26.1 KB
    __shared__ __align__(16) float x2[ROWS][84];    // 10.8 KB

    const float4* src = (const float4*)(g_feat + (size_t)row0 * FEAT);
    for (int i = t; i < ROWS * FEAT / 4; i += 256) {
        float4 v = src[i];
        int r = i >> 5, c = (i & 31) * 4;
        fs[r][c] = v.x; fs[r][c + 1] = v.y;
        fs[r][c + 2] = v.z; fs[r][c + 3] = v.w;
    }
    __syncthreads();

    // fc1: 200 threads: jjq = t%50 (4 jj), rowgroup = (t/50)*8 (8 rows)
    if (t < 200) {
        const int jjq = t % 50;
        const int rg  = (t / 50) * 8;
        const float* wbase = fw1 + 4 * jjq;
        const ull b0  = pk(fb1[4 * jjq],     fb1[4 * jjq + 1]);
        const ull b1v = pk(fb1[4 * jjq + 2], fb1[4 * jjq + 3]);
        ull acc[8][2];
#pragma unroll
        for (int r = 0; r < 8; r++) { acc[r][0] = b0; acc[r][1] = b1v; }
#pragma unroll 4
        for (int i = 0; i < FEAT; i++) {
            float4 wv = __ldg((const float4*)(wbase + i * 200));
            ull wp0 = pk(wv.x, wv.y);
            ull wp1 = pk(wv.z, wv.w);
#pragma unroll
            for (int r = 0; r < 8; r++) {
                float xv = fs[rg + r][i];
                ull xx = pk(xv, xv);
                ffma2(acc[r][0], xx, wp0);
                ffma2(acc[r][1], xx, wp1);
            }
        }
#pragma unroll
        for (int r = 0; r < 8; r++) {
            float h0, h1, h2, h3;
            upk(acc[r][0], h0, h1);
            upk(acc[r][1], h2, h3);
            float4 o;
            o.x = fmaxf(h0, 0.f); o.y = fmaxf(h1, 0.f);
            o.z = fmaxf(h2, 0.f); o.w = fmaxf(h3, 0.f);
            *(float4*)&x1[rg + r][4 * jjq] = o;
        }
    }
    __syncthreads();

    // fc2: 160 threads: jjq = t%20 (4 jj), rowgroup = (t/20)*4 (4 rows)
    if (t < 160) {
        const int jjq = t % 20;
        const int rg  = (t / 20) * 4;
        const float* wbase = fw2 + 4 * jjq;
        const ull b0  = pk(fb2[4 * jjq],     fb2[4 * jjq + 1]);
        const ull b1v = pk(fb2[4 * jjq + 2], fb2[4 * jjq + 3]);
        ull acc[4][2];
#pragma unroll
        for (int r = 0; r < 4; r++) { acc[r][0] = b0; acc[r][1] = b1v; }
#pragma unroll 4
        for (int i = 0; i < 200; i++) {
            float4 wv = __ldg((const float4*)(wbase + i * 80));
            ull wp0 = pk(wv.x, wv.y);
            ull wp1 = pk(wv.z, wv.w);
#pragma unroll
            for (int r = 0; r < 4; r++) {
                float xv = x1[rg + r][i];
                ull xx = pk(xv, xv);
                ffma2(acc[r][0], xx, wp0);
                ffma2(acc[r][1], xx, wp1);
            }
        }
#pragma unroll
        for (int r = 0; r < 4; r++) {
            float h0, h1, h2, h3;
            upk(acc[r][0], h0, h1);
            upk(acc[r][1], h2, h3);
            float4 o;
            o.x = fmaxf(h0, 0.f); o.y = fmaxf(h1, 0.f);
            o.z = fmaxf(h2, 0.f); o.w = fmaxf(h3, 0.f);
            *(float4*)&x2[rg + r][4 * jjq] = o;
        }
    }
    __syncthreads();

    // fc3 + sigmoid (32 rows)
    if (t < ROWS) {
        const ull* wp = (const ull*)fw3;
        const ull* xp = (const ull*)&x2[t][0];
        ull acc = 0ull;
#pragma unroll
        for (int ip = 0; ip < 40; ip++)
            ffma2(acc, xp[ip], __ldg(&wp[ip]));
        float a, b;
        upk(acc, a, b);
        float s = a + b + fb3[0];
        g_logits[row0 + t] = 1.0f / (1.0f + expf(-s));
    }

    // ---- fused softmax: last fc group (of 8) per batch runs it ----
    __threadfence();
    __syncthreads();
    __shared__ int sb_flag;
    if (t == 0) {
        int old = atomicAdd(&g_cnt_b[row0 >> 8], 1);
        sb_flag = (old == 7);
    }
    __syncthreads();
    if (!sb_flag) return;
    __threadfence();   // acquire: make other groups' logits visible

    const int base = (row0 >> 8) * NN;
    const int wid = t >> 5, lane = t & 31;
    __shared__ float red[8];
    __shared__ float smx, ssum;

    float l = g_logits[base + t];
    bool masked = (items[base + t] == 0);
    float val = masked ? -FLT_MAX : l;

    float mx = val;
#pragma unroll
    for (int o = 16; o > 0; o >>= 1)
        mx = fmaxf(mx, __shfl_down_sync(0xffffffffu, mx, o));
    if (lane == 0) red[wid] = mx;
    __syncthreads();
    if (t == 0) {
        float m = red[0];
#pragma unroll
        for (int w2i = 1; w2i < 8; w2i++) m = fmaxf(m, red[w2i]);
        smx = m;
    }
    __syncthreads();
    float m = smx;

    float e = masked ? 0.0f : expf(l - m);
    float sum = e;
#pragma unroll
    for (int o = 16; o > 0; o >>= 1)
        sum += __shfl_down_sync(0xffffffffu, sum, o);
    if (lane == 0) red[wid] = sum;
    __syncthreads();
    if (t == 0) {
        float s = 0.0f;
#pragma unroll
        for (int w2i = 0; w2i < 8; w2i++) s += red[w2i];
        ssum = s;
    }
    __syncthreads();

    out[base + t] = e / ssum;
}

// ---------------- launch ----------------
extern "C" void kernel_launch(void* const* d_in, const int* in_sizes, int n_in,
                              void* d_out, int out_size)
{
    const float* emb_user  = (const float*)d_in[0];
    const float* emb_item  = (const float*)d_in[1];
    const float* emb_cate  = (const float*)d_in[2];
    const float* att_w1    = (const float*)d_in[3];
    const float* att_b1    = (const float*)d_in[4];
    const float* att_w2    = (const float*)d_in[5];
    const float* att_b2    = (const float*)d_in[6];
    const float* att_w3    = (const float*)d_in[7];
    const float* att_b3    = (const float*)d_in[8];
    const float* fc_w1     = (const float*)d_in[9];
    const float* fc_b1     = (const float*)d_in[10];
    const float* fc_w2     = (const float*)d_in[11];
    const float* fc_b2     = (const float*)d_in[12];
    const float* fc_w3     = (const float*)d_in[13];
    const float* fc_b3     = (const float*)d_in[14];
    const int*   user      = (const int*)d_in[15];
    const int*   items     = (const int*)d_in[16];
    const int*   items_cate= (const int*)d_in[17];
    const int*   ii        = (const int*)d_in[18];
    const int*   iic       = (const int*)d_in[19];
    float* out = (float*)d_out;

    setup_kernel<<<7, 256>>>(att_w1, att_w2, att_w3, att_b2, att_b3);
    attn_kernel<<<BN, 128>>>(emb_user, emb_item, emb_cate, att_b1,
                             user, items, items_cate, ii, iic);
    fc_kernel<<<BN / ROWS, 256>>>(fc_w1, fc_b1, fc_w2, fc_b2, fc_w3, fc_b3,
                                  items, out);
}

// round 16
// speedup vs baseline: 1.0758x; 1.0511x over previous
#include <cuda_runtime.h>
#include <cuda_bf16.h>
#include <cfloat>
#include <cmath>

#define BB 32
#define NN 256
#define LL 50
#define BN (BB * NN)          // 8192
#define DU 32
#define DI 32
#define DC 16
#define DD 48
#define FEAT 128

typedef unsigned long long ull;

// ---------------- scratch (no allocs allowed) ----------------
__device__ float g_feat[BN * FEAT];
__device__ float g_logits[BN];
__device__ __align__(16) ull g_Wbc2[24 * 64]; // (b-c) k-pairs, [kp][j]
__device__ __align__(16) ull g_Wac2[24 * 64]; // (a+c) k-pairs
__device__ __align__(16) ull g_Wd2 [24 * 64]; // d k-pairs
__device__ float g_v[64];                     // w2 @ w3
__device__ float g_cs[1];                     // b2.w3 + b3
__device__ int   g_cnt_b[BB];                 // batch completion counters

// ---------------- helpers ----------------
__device__ __forceinline__ void ffma2(ull& acc, ull a, ull b) {
    asm("fma.rn.f32x2 %0, %1, %2, %0;" : "+l"(acc) : "l"(a), "l"(b));
}
__device__ __forceinline__ void upk(ull v, float& x, float& y) {
    asm("mov.b64 {%0,%1}, %2;" : "=f"(x), "=f"(y) : "l"(v));
}
__device__ __forceinline__ ull pk(float x, float y) {
    ull r;
    asm("mov.b64 %0, {%1,%2};" : "=l"(r) : "f"(x), "f"(y));
    return r;
}
__device__ __forceinline__ unsigned sptr(const void* p) {
    return (unsigned)__cvta_generic_to_shared(p);
}
__device__ __forceinline__ void lds_v2u64(unsigned addr, ull& a, ull& b) {
    asm("ld.shared.v2.u64 {%0,%1}, [%2];" : "=l"(a), "=l"(b) : "r"(addr));
}
__device__ __forceinline__ void sts_u64(unsigned addr, ull v) {
    asm("st.shared.u64 [%0], %1;" :: "r"(addr), "l"(v));
}
__device__ __forceinline__ void cpasync16(unsigned dst, const void* src) {
    asm volatile("cp.async.ca.shared.global [%0], [%1], 16;"
                 :: "r"(dst), "l"(src));
}
__device__ __forceinline__ void cpasync_wait_all() {
    asm volatile("cp.async.commit_group;\ncp.async.wait_group 0;" ::: "memory");
}

// ---------------- K0: fold weights + zero counters ----------------
__global__ void setup_kernel(const float* __restrict__ w1,
                             const float* __restrict__ w2,
                             const float* __restrict__ w3,
                             const float* __restrict__ b2,
                             const float* __restrict__ b3)
{
    int e = blockIdx.x * 256 + threadIdx.x;
    if (blockIdx.x < 6) {           // 1536 elements: (kp, j)
        int kp = e / 64, j = e % 64;
        int k0 = 2 * kp, k1 = 2 * kp + 1;
        float a0 = w1[k0 * 64 + j];
        float b0 = w1[(48 + k0) * 64 + j];
        float c0 = w1[(96 + k0) * 64 + j];
        float d0 = w1[(144 + k0) * 64 + j];
        float a1 = w1[k1 * 64 + j];
        float bb1 = w1[(48 + k1) * 64 + j];
        float c1 = w1[(96 + k1) * 64 + j];
        float d1 = w1[(144 + k1) * 64 + j];
        g_Wbc2[e] = pk(b0 - c0, bb1 - c1);
        g_Wac2[e] = pk(a0 + c0, a1 + c1);
        g_Wd2[e]  = pk(d0, d1);
    } else {
        int t = threadIdx.x;
        if (t < 64) {
            float v = 0.f;
#pragma unroll
            for (int m = 0; m < 16; m++) v += w2[t * 16 + m] * w3[m];
            g_v[t] = v;
        } else if (t == 64) {
            float cs = b3[0];
#pragma unroll
            for (int m = 0; m < 16; m++) cs += b2[m] * w3[m];
            g_cs[0] = cs;
        }
        if (t >= 128 && t < 128 + BB) g_cnt_b[t - 128] = 0;
    }
}

// ---------------- K1: attention ----------------
// Occupancy-raised variant: lane owns a CONTIGUOUS column pair
//   jp = (lane&15) + 16*(w&1)  -> cols {2jp, 2jp+1}, k-half = lane>>4.
// Warp-pair covers all 64 columns; warp w covers l-chunk (w>>1)*25.
// A-tile = 24 ull = 48 regs -> ~80 regs/thread -> 6 CTAs/SM.
__global__ void __launch_bounds__(128, 6) attn_kernel(
    const float* __restrict__ emb_user,
    const float* __restrict__ emb_item,
    const float* __restrict__ emb_cate,
    const float* __restrict__ b1,
    const int* __restrict__ user,
    const int* __restrict__ items,
    const int* __restrict__ items_cate,
    const int* __restrict__ ii,
    const int* __restrict__ iic)
{
    const int bn    = blockIdx.x;
    const int t     = threadIdx.x;
    const int w     = t >> 5;
    const int lane  = t & 31;
    const int jp    = (lane & 15) + 16 * (w & 1);
    const int khalf = lane >> 4;

    __shared__ __align__(16) float q_s[48];
    __shared__ __align__(16) ull Mx[24 * 64]; // [kp][j]
    __shared__ float cn_part[2][64];
    __shared__ float v_s[64];
    __shared__ __align__(16) float he_s[LL][52];
    __shared__ __align__(16) float S[LL][36];   // 144B rows (16B-aligned halves)
    __shared__ float sc_s[LL];
    __shared__ int   idx_s[LL];

    // ================= phase 1 (no barrier until cp.async wait) ==========
    {
        const unsigned heb = sptr(he_s);
#pragma unroll
        for (int u = 0; u < 5; u++) {
            int idx = t + u * 128;
            if (idx < LL * 12) {
                int row = idx / 12, c = idx % 12;
                const float* src;
                if (c < 8) {
                    int e = __ldg(&ii[bn * LL + row]);
                    src = emb_item + (size_t)e * DI + c * 4;
                } else {
                    int e = __ldg(&iic[bn * LL + row]);
                    src = emb_cate + (size_t)e * DC + (c - 8) * 4;
                }
                cpasync16(heb + row * 208 + c * 16, src);
            }
        }
    }

    {
        const int it = __ldg(&items[bn]);
        const int ic = __ldg(&items_cate[bn]);
        if (t < 32)       q_s[t] = __ldg(&emb_item[(size_t)it * DI + t]);
        else if (t < 48)  q_s[t] = __ldg(&emb_cate[(size_t)ic * DC + (t - 32)]);
        if (t < 64)       v_s[t] = g_v[t];
        if (t >= 64 && t < 64 + LL) idx_s[t - 64] = __ldg(&ii[bn * LL + (t - 64)]);
    }

    // fold (coalesced): j = t&63, k-half = t>>6
    {
        const int j = t & 63;
        const int half = t >> 6;
        const int it = __ldg(&items[bn]);
        const int ic = __ldg(&items_cate[bn]);
        const ull* qitem = (const ull*)(emb_item + (size_t)it * DI);
        const ull* qcate = (const ull*)(emb_cate + (size_t)ic * DC);
        const ull* wbcp = g_Wbc2 + half * 12 * 64 + j;
        const ull* wacp = g_Wac2 + half * 12 * 64 + j;
        const ull* wdp  = g_Wd2  + half * 12 * 64 + j;
        unsigned mxb = sptr(Mx) + j * 8 + half * 12 * 512;
        ull cnacc = 0ull;
#pragma unroll
        for (int kp = 0; kp < 12; kp++) {
            const int kpg = half * 12 + kp;
            ull qp = (kpg < 16) ? __ldg(&qitem[kpg]) : __ldg(&qcate[kpg - 16]);
            ull m = __ldg(&wbcp[kp * 64]);
            ffma2(m, qp, __ldg(&wdp[kp * 64]));
            sts_u64(mxb + kp * 512, m);
            ffma2(cnacc, qp, __ldg(&wacp[kp * 64]));
        }
        float cx, cy;
        upk(cnacc, cx, cy);
        cn_part[half][j] = cx + cy + ((half == 0) ? b1[j] : 0.f);
    }
    cpasync_wait_all();
    __syncthreads();

    // ================= phase 2: score ======================================
    // A-tile: cols {2jp, 2jp+1}, my 24 k values = 24 u64 (lane-contiguous).
    ull A0[12], A1[12];
    {
        unsigned mb = sptr(Mx) + khalf * 12 * 512 + jp * 16;
#pragma unroll
        for (int i = 0; i < 12; i++)
            lds_v2u64(mb + i * 512, A0[i], A1[i]);
    }
    const int c0 = 2 * jp;
    const float cn0 = cn_part[0][c0]     + cn_part[1][c0];
    const float cn1 = cn_part[0][c0 + 1] + cn_part[1][c0 + 1];
    const float v0 = v_s[c0], v1 = v_s[c0 + 1];

    const int l0 = (w >> 1) * 25;
    for (int li = 0; li < 25; li++) {
        const int l = l0 + li;
        unsigned hb = sptr(&he_s[l][0]) + khalf * 96;
        ull a0 = 0ull, a1 = 0ull;
#pragma unroll
        for (int c = 0; c < 6; c++) {
            ull h0, h1;
            lds_v2u64(hb + c * 16, h0, h1);
            ffma2(a0, h0, A0[2 * c]);
            ffma2(a0, h1, A0[2 * c + 1]);
            ffma2(a1, h0, A1[2 * c]);
            ffma2(a1, h1, A1[2 * c + 1]);
        }
        float x, y;
        upk(a0, x, y); float p0 = x + y;
        upk(a1, x, y); float p1 = x + y;
        p0 += __shfl_xor_sync(0xffffffffu, p0, 16);
        p1 += __shfl_xor_sync(0xffffffffu, p1, 16);
        float s = fmaxf(p0 + cn0, 0.f) * v0;
        s = fmaf(fmaxf(p1 + cn1, 0.f), v1, s);
        S[l][jp] = s;   // both k-halves write the same value (benign)
    }
    __syncthreads();

    // ================= phase 3: score reduce (32 partials, contiguous) ====
    if (t < 100) {
        const int l = t >> 1, h = t & 1;
        const float4* sp = (const float4*)&S[l][h * 16];
        float4 r0 = sp[0], r1 = sp[1], r2 = sp[2], r3 = sp[3];
        float s16 = ((r0.x + r0.y) + (r0.z + r0.w))
                  + ((r1.x + r1.y) + (r1.z + r1.w))
                  + ((r2.x + r2.y) + (r2.z + r2.w))
                  + ((r3.x + r3.y) + (r3.z + r3.w));
        unsigned mk = (t < 96) ? 0xffffffffu : 0xfu;
        float tot = s16 + __shfl_xor_sync(mk, s16, 1);
        if (h == 0)
            sc_s[l] = (idx_s[l] == 0) ? 0.f : (tot + g_cs[0]);
    }
    __syncthreads();

    // ================= phase 4: pooled + feat ==============================
    float* fo = g_feat + bn * FEAT;
    if (t < 48) {
        float pooled = 0.f;
#pragma unroll 10
        for (int l = 0; l < LL; l++)
            pooled = fmaf(sc_s[l], he_s[l][t], pooled);
        fo[t]      = q_s[t];
        fo[48 + t] = pooled;
    } else if (t < 80) {
        fo[96 + (t - 48)] = __ldg(&emb_user[(size_t)__ldg(&user[bn]) * DU + (t - 48)]);
    }
}

// ---------------- K2: FC MLP (32 rows/CTA) + fused softmax ----------------
#define ROWS 32
__global__ void __launch_bounds__(256) fc_kernel(
    const float* __restrict__ fw1, const float* __restrict__ fb1,
    const float* __restrict__ fw2, const float* __restrict__ fb2,
    const float* __restrict__ fw3, const float* __restrict__ fb3,
    const int* __restrict__ items, float* __restrict__ out)
{
    const int t = threadIdx.x;
    const int row0 = blockIdx.x * ROWS;

    __shared__ __align__(16) float fs[ROWS][132];
    __shared__ __align__(16) float x1[ROWS][204];
    __shared__ __align__(16) float x2[ROWS][84];

    const float4* src = (const float4*)(g_feat + (size_t)row0 * FEAT);
    for (int i = t; i < ROWS * FEAT / 4; i += 256) {
        float4 v = src[i];
        int r = i >> 5, c = (i & 31) * 4;
        fs[r][c] = v.x; fs[r][c + 1] = v.y;
        fs[r][c + 2] = v.z; fs[r][c + 3] = v.w;
    }
    __syncthreads();

    if (t < 200) {
        const int jjq = t % 50;
        const int rg  = (t / 50) * 8;
        const float* wbase = fw1 + 4 * jjq;
        const ull b0  = pk(fb1[4 * jjq],     fb1[4 * jjq + 1]);
        const ull b1v = pk(fb1[4 * jjq + 2], fb1[4 * jjq + 3]);
        ull acc[8][2];
#pragma unroll
        for (int r = 0; r < 8; r++) { acc[r][0] = b0; acc[r][1] = b1v; }
#pragma unroll 4
        for (int i = 0; i < FEAT; i++) {
            float4 wv = __ldg((const float4*)(wbase + i * 200));
            ull wp0 = pk(wv.x, wv.y);
            ull wp1 = pk(wv.z, wv.w);
#pragma unroll
            for (int r = 0; r < 8; r++) {
                float xv = fs[rg + r][i];
                ull xx = pk(xv, xv);
                ffma2(acc[r][0], xx, wp0);
                ffma2(acc[r][1], xx, wp1);
            }
        }
#pragma unroll
        for (int r = 0; r < 8; r++) {
            float h0, h1, h2, h3;
            upk(acc[r][0], h0, h1);
            upk(acc[r][1], h2, h3);
            float4 o;
            o.x = fmaxf(h0, 0.f); o.y = fmaxf(h1, 0.f);
            o.z = fmaxf(h2, 0.f); o.w = fmaxf(h3, 0.f);
            *(float4*)&x1[rg + r][4 * jjq] = o;
        }
    }
    __syncthreads();

    if (t < 160) {
        const int jjq = t % 20;
        const int rg  = (t / 20) * 4;
        const float* wbase = fw2 + 4 * jjq;
        const ull b0  = pk(fb2[4 * jjq],     fb2[4 * jjq + 1]);
        const ull b1v = pk(fb2[4 * jjq + 2], fb2[4 * jjq + 3]);
        ull acc[4][2];
#pragma unroll
        for (int r = 0; r < 4; r++) { acc[r][0] = b0; acc[r][1] = b1v; }
#pragma unroll 4
        for (int i = 0; i < 200; i++) {
            float4 wv = __ldg((const float4*)(wbase + i * 80));
            ull wp0 = pk(wv.x, wv.y);
            ull wp1 = pk(wv.z, wv.w);
#pragma unroll
            for (int r = 0; r < 4; r++) {
                float xv = x1[rg + r][i];
                ull xx = pk(xv, xv);
                ffma2(acc[r][0], xx, wp0);
                ffma2(acc[r][1], xx, wp1);
            }
        }
#pragma unroll
        for (int r = 0; r < 4; r++) {
            float h0, h1, h2, h3;
            upk(acc[r][0], h0, h1);
            upk(acc[r][1], h2, h3);
            float4 o;
            o.x = fmaxf(h0, 0.f); o.y = fmaxf(h1, 0.f);
            o.z = fmaxf(h2, 0.f); o.w = fmaxf(h3, 0.f);
            *(float4*)&x2[rg + r][4 * jjq] = o;
        }
    }
    __syncthreads();

    if (t < ROWS) {
        const ull* wp = (const ull*)fw3;
        const ull* xp = (const ull*)&x2[t][0];
        ull acc = 0ull;
#pragma unroll
        for (int ip = 0; ip < 40; ip++)
            ffma2(acc, xp[ip], __ldg(&wp[ip]));
        float a, b;
        upk(acc, a, b);
        float s = a + b + fb3[0];
        g_logits[row0 + t] = 1.0f / (1.0f + expf(-s));
    }

    // ---- fused softmax: last fc group (of 8) per batch runs it ----
    __threadfence();
    __syncthreads();
    __shared__ int sb_flag;
    if (t == 0) {
        int old = atomicAdd(&g_cnt_b[row0 >> 8], 1);
        sb_flag = (old == 7);
    }
    __syncthreads();
    if (!sb_flag) return;
    __threadfence();   // acquire

    const int base = (row0 >> 8) * NN;
    const int wid = t >> 5, lane = t & 31;
    __shared__ float red[8];
    __shared__ float smx, ssum;

    float l = g_logits[base + t];
    bool masked = (items[base + t] == 0);
    float val = masked ? -FLT_MAX : l;

    float mx = val;
#pragma unroll
    for (int o = 16; o > 0; o >>= 1)
        mx = fmaxf(mx, __shfl_down_sync(0xffffffffu, mx, o));
    if (lane == 0) red[wid] = mx;
    __syncthreads();
    if (t == 0) {
        float m = red[0];
#pragma unroll
        for (int w2i = 1; w2i < 8; w2i++) m = fmaxf(m, red[w2i]);
        smx = m;
    }
    __syncthreads();
    float m = smx;

    float e = masked ? 0.0f : expf(l - m);
    float sum = e;
#pragma unroll
    for (int o = 16; o > 0; o >>= 1)
        sum += __shfl_down_sync(0xffffffffu, sum, o);
    if (lane == 0) red[wid] = sum;
    __syncthreads();
    if (t == 0) {
        float s = 0.0f;
#pragma unroll
        for (int w2i = 0; w2i < 8; w2i++) s += red[w2i];
        ssum = s;
    }
    __syncthreads();

    out[base + t] = e / ssum;
}

// ---------------- launch ----------------
extern "C" void kernel_launch(void* const* d_in, const int* in_sizes, int n_in,
                              void* d_out, int out_size)
{
    const float* emb_user  = (const float*)d_in[0];
    const float* emb_item  = (const float*)d_in[1];
    const float* emb_cate  = (const float*)d_in[2];
    const float* att_w1    = (const float*)d_in[3];
    const float* att_b1    = (const float*)d_in[4];
    const float* att_w2    = (const float*)d_in[5];
    const float* att_b2    = (const float*)d_in[6];
    const float* att_w3    = (const float*)d_in[7];
    const float* att_b3    = (const float*)d_in[8];
    const float* fc_w1     = (const float*)d_in[9];
    const float* fc_b1     = (const float*)d_in[10];
    const float* fc_w2     = (const float*)d_in[11];
    const float* fc_b2     = (const float*)d_in[12];
    const float* fc_w3     = (const float*)d_in[13];
    const float* fc_b3     = (const float*)d_in[14];
    const int*   user      = (const int*)d_in[15];
    const int*   items     = (const int*)d_in[16];
    const int*   items_cate= (const int*)d_in[17];
    const int*   ii        = (const int*)d_in[18];
    const int*   iic       = (const int*)d_in[19];
    float* out = (float*)d_out;

    setup_kernel<<<7, 256>>>(att_w1, att_w2, att_w3, att_b2, att_b3);
    attn_kernel<<<BN, 128>>>(emb_user, emb_item, emb_cate, att_b1,
                             user, items, items_cate, ii, iic);
    fc_kernel<<<BN / ROWS, 256>>>(fc_w1, fc_b1, fc_w2, fc_b2, fc_w3, fc_b3,
                                  items, out);
}